// round 2
// baseline (speedup 1.0000x reference)
#include <cuda_runtime.h>
#include <cstdint>

// Problem constants (fixed shapes)
#define NROWS 32768        // B*T
#define KCODES 8192
#define DDIM 256
#define GAMMA_F 0.99f
#define ONE_MG 0.01f
#define EPS_F 1e-5f
#define KEPS_F 0.08192f    // K * EPS

// Output layout (flattened tuple, float32)
#define OFF_ZQ     ((size_t)0)
#define OFF_COMMIT ((size_t)8388608)
#define OFF_IDX    ((size_t)8388609)
#define OFF_EW     ((size_t)8421377)
#define OFF_MT     ((size_t)10518529)
#define OFF_NT     ((size_t)12615681)

// Scratch (device globals — no allocation allowed)
__device__ float  g_wnorm[KCODES];
__device__ int    g_idx[NROWS];
__device__ double g_commit;
__device__ float  g_n;

// ---- packed f32x2 helpers ----
#define PACK_DUP(out64, f32val) do {                                   \
    unsigned int _u = __float_as_uint(f32val);                         \
    asm("mov.b64 %0, {%1, %1};" : "=l"(out64) : "r"(_u));              \
} while (0)

#define FMA2(acc, a, b)                                                \
    asm("fma.rn.f32x2 %0, %1, %2, %0;" : "+l"(acc) : "l"(a), "l"(b))

#define UNPACK2(lo, hi, v64) do {                                      \
    unsigned int _l, _h;                                               \
    asm("mov.b64 {%0, %1}, %2;" : "=r"(_l), "=r"(_h) : "l"(v64));      \
    lo = __uint_as_float(_l); hi = __uint_as_float(_h);                \
} while (0)

// ---------------------------------------------------------------------------
__global__ void k_init(const float* __restrict__ mt, const float* __restrict__ Nt,
                       float* __restrict__ out)
{
    int i = blockIdx.x * blockDim.x + threadIdx.x;
    if (i == 0) g_commit = 0.0;
    if (i < KCODES) out[OFF_NT + i] = GAMMA_F * Nt[i];
    const int total = KCODES * DDIM;
    const int stride = gridDim.x * blockDim.x;
    for (int j = i; j < total; j += stride)
        out[OFF_MT + j] = GAMMA_F * mt[j];
}

// ---------------------------------------------------------------------------
__global__ void k_wnorm(const float* __restrict__ W)
{
    int warp = (blockIdx.x * blockDim.x + threadIdx.x) >> 5;
    int lane = threadIdx.x & 31;
    if (warp >= KCODES) return;
    const float* w = W + (size_t)warp * DDIM;
    float s = 0.f;
#pragma unroll
    for (int j = 0; j < 8; j++) { float v = w[lane + 32 * j]; s = fmaf(v, v, s); }
#pragma unroll
    for (int off = 16; off >= 1; off >>= 1)
        s += __shfl_xor_sync(0xffffffffu, s, off);
    if (lane == 0) g_wnorm[warp] = s;
}

// ---------------------------------------------------------------------------
// k_argmin: 32768 x 8192 x 256 distance GEMM + running argmin.
// CTA tile 128 rows x 128 codes; K processed in 512 chunks of 32 (flattened
// over 64 code-tiles x 8 k-chunks). Single-barrier double-buffered SMEM
// pipeline; packed fma.rn.f32x2 inner loop (codes paired).
// Thread (tx,ty) owns rows ty*8..+7 and codes {4tx..4tx+3, 64+4tx..64+4tx+3}
// so b-fragments are contiguous 256B reads (conflict-minimal).
// ---------------------------------------------------------------------------
#define SROW 132            // floats per smem row (32B-pad; 528B, 16B-aligned)
#define SMEM_FLOATS (2 * 2 * 32 * SROW)

__global__ __launch_bounds__(256, 2)
void k_argmin(const float* __restrict__ ze, const float* __restrict__ W,
              float* __restrict__ out_idx)
{
    extern __shared__ float smem[];
    float (*sZ)[32][SROW] = (float (*)[32][SROW])smem;                  // [2][32][SROW]
    float (*sW)[32][SROW] = (float (*)[32][SROW])(smem + 2 * 32 * SROW);

    const int t  = threadIdx.x;
    const int tx = t & 15;
    const int ty = t >> 4;
    const int rowBase = blockIdx.x * 128;

    float minv[8];
    int   mini[8];
#pragma unroll
    for (int i = 0; i < 8; i++) { minv[i] = 3.4e38f; mini[i] = 0; }

    float4 zf[4], wf[4];

#define LDG_CHUNK(m) do {                                                      \
    int _cB  = ((m) >> 3) * 128;                                               \
    int _dkb = ((m) & 7) * 32;                                                 \
    _Pragma("unroll")                                                          \
    for (int _i = 0; _i < 4; _i++) {                                           \
        int _f = t + 256 * _i;                                                 \
        int _r = _f >> 3, _d4 = _f & 7;                                        \
        zf[_i] = *(const float4*)&ze[(size_t)(rowBase + _r) * DDIM + _dkb + 4 * _d4]; \
        wf[_i] = *(const float4*)&W [(size_t)(_cB     + _r) * DDIM + _dkb + 4 * _d4]; \
    }                                                                          \
} while (0)

#define STS_CHUNK(nb) do {                                                     \
    _Pragma("unroll")                                                          \
    for (int _i = 0; _i < 4; _i++) {                                           \
        int _f = t + 256 * _i;                                                 \
        int _r = _f >> 3, _d4 = _f & 7;                                        \
        const float* _zp = (const float*)&zf[_i];                              \
        const float* _wp = (const float*)&wf[_i];                              \
        _Pragma("unroll")                                                      \
        for (int _j = 0; _j < 4; _j++) {                                       \
            sZ[nb][_d4 * 4 + _j][_r] = _zp[_j];                                \
            sW[nb][_d4 * 4 + _j][_r] = _wp[_j];                                \
        }                                                                      \
    }                                                                          \
} while (0)

    // pipeline prologue
    LDG_CHUNK(0);
    STS_CHUNK(0);
    __syncthreads();

    unsigned long long acc[8][4];
#pragma unroll
    for (int i = 0; i < 8; i++)
#pragma unroll
        for (int j = 0; j < 4; j++) acc[i][j] = 0ull;

    for (int m = 0; m < 512; ++m) {
        if (m < 511) LDG_CHUNK(m + 1);

        const int buf = m & 1;
#pragma unroll 8
        for (int kk = 0; kk < 32; ++kk) {
            // b: contiguous 256B fragments (codes 4tx.., 64+4tx..)
            ulonglong2 b01 = *(const ulonglong2*)&sW[buf][kk][4 * tx];
            ulonglong2 b23 = *(const ulonglong2*)&sW[buf][kk][64 + 4 * tx];
            // a: broadcast row fragment
            float4 a0 = *(const float4*)&sZ[buf][kk][8 * ty];
            float4 a1 = *(const float4*)&sZ[buf][kk][8 * ty + 4];
            float av[8] = {a0.x, a0.y, a0.z, a0.w, a1.x, a1.y, a1.z, a1.w};
#pragma unroll
            for (int i = 0; i < 8; i++) {
                unsigned long long ap;
                PACK_DUP(ap, av[i]);
                FMA2(acc[i][0], ap, b01.x);
                FMA2(acc[i][1], ap, b01.y);
                FMA2(acc[i][2], ap, b23.x);
                FMA2(acc[i][3], ap, b23.y);
            }
        }

        if ((m & 7) == 7) {
            // finished K for this 128-code tile -> distances + argmin update
            const int cBase = (m >> 3) * 128;
#pragma unroll
            for (int p = 0; p < 4; p++) {
                int c0 = cBase + 4 * tx + ((p < 2) ? 2 * p : 64 + 2 * (p - 2));
                float w0 = g_wnorm[c0], w1 = g_wnorm[c0 + 1];
#pragma unroll
                for (int i = 0; i < 8; i++) {
                    float lo, hi;
                    UNPACK2(lo, hi, acc[i][p]);
                    float d0 = w0 - 2.0f * lo;
                    float d1 = w1 - 2.0f * hi;
                    if (d0 < minv[i]) { minv[i] = d0; mini[i] = c0; }
                    if (d1 < minv[i]) { minv[i] = d1; mini[i] = c0 + 1; }
                    acc[i][p] = 0ull;
                }
            }
        }

        if (m < 511) STS_CHUNK((m + 1) & 1);
        __syncthreads();
    }

    // reduce argmin across the 16 tx lanes (lowest value; tie -> lowest index)
#pragma unroll
    for (int i = 0; i < 8; i++) {
        float v = minv[i]; int ix = mini[i];
#pragma unroll
        for (int off = 8; off >= 1; off >>= 1) {
            float ov = __shfl_xor_sync(0xffffffffu, v, off);
            int   oi = __shfl_xor_sync(0xffffffffu, ix, off);
            if (ov < v || (ov == v && oi < ix)) { v = ov; ix = oi; }
        }
        if (tx == 0) {
            int row = rowBase + ty * 8 + i;
            g_idx[row] = ix;
            out_idx[row] = (float)ix;
        }
    }
#undef LDG_CHUNK
#undef STS_CHUNK
}

// ---------------------------------------------------------------------------
__global__ void k_gather(const float* __restrict__ ze, const float* __restrict__ W,
                         float* __restrict__ out)
{
    int wInB = threadIdx.x >> 5;
    int lane = threadIdx.x & 31;
    int row  = blockIdx.x * 8 + wInB;
    int idx  = g_idx[row];
    const float* z = ze + (size_t)row * DDIM;
    const float* w = W  + (size_t)idx * DDIM;
    float c = 0.f;
#pragma unroll
    for (int j = 0; j < 8; j++) {
        int d = lane + 32 * j;
        float wv = w[d], zv = z[d];
        float df = wv - zv;
        out[OFF_ZQ + (size_t)row * DDIM + d] = zv + df;
        c = fmaf(df, df, c);
        atomicAdd(&out[OFF_MT + (size_t)idx * DDIM + d], ONE_MG * zv);
    }
#pragma unroll
    for (int off = 16; off >= 1; off >>= 1)
        c += __shfl_xor_sync(0xffffffffu, c, off);
    if (lane == 0) {
        atomicAdd(&g_commit, (double)c);
        atomicAdd(&out[OFF_NT + idx], ONE_MG);
    }
}

// ---------------------------------------------------------------------------
__global__ void k_reduce(float* __restrict__ out)
{
    __shared__ float sb[256];
    float s = 0.f;
    for (int i = threadIdx.x; i < KCODES; i += 256) s += out[OFF_NT + i];
    sb[threadIdx.x] = s;
    __syncthreads();
    for (int off = 128; off >= 1; off >>= 1) {
        if (threadIdx.x < off) sb[threadIdx.x] += sb[threadIdx.x + off];
        __syncthreads();
    }
    if (threadIdx.x == 0) {
        g_n = sb[0];
        out[OFF_COMMIT] = (float)(g_commit / (double)(NROWS * DDIM));
    }
}

// ---------------------------------------------------------------------------
__global__ void k_final(float* __restrict__ out)
{
    int i = blockIdx.x * blockDim.x + threadIdx.x;
    if (i >= KCODES * DDIM) return;
    int k = i >> 8;
    float n  = g_n;
    float nt = out[OFF_NT + k];
    float scale = (n + KEPS_F) / ((nt + EPS_F) * n);
    out[OFF_EW + i] = out[OFF_MT + i] * scale;
}

// ---------------------------------------------------------------------------
extern "C" void kernel_launch(void* const* d_in, const int* in_sizes, int n_in,
                              void* d_out, int out_size)
{
    const float* ze = (const float*)d_in[0];
    const float* W  = (const float*)d_in[1];
    const float* mt = (const float*)d_in[2];
    const float* Nt = (const float*)d_in[3];
    float* out = (float*)d_out;

    const int smem_bytes = SMEM_FLOATS * (int)sizeof(float);  // 67,584 B
    cudaFuncSetAttribute(k_argmin, cudaFuncAttributeMaxDynamicSharedMemorySize, smem_bytes);

    k_init  <<<2048, 256>>>(mt, Nt, out);
    k_wnorm <<<(KCODES * 32) / 256, 256>>>(W);
    k_argmin<<<NROWS / 128, 256, smem_bytes>>>(ze, W, out + OFF_IDX);
    k_gather<<<NROWS / 8, 256>>>(ze, W, out);
    k_reduce<<<1, 256>>>(out);
    k_final <<<(KCODES * DDIM) / 256, 256>>>(out);
}